// round 9
// baseline (speedup 1.0000x reference)
#include <cuda_runtime.h>
#include <cstdint>

// Problem constants (fixed by the reference)
#define NG 128      // num_graphs
#define NT 32       // num thetas
#define NS 32       // bump steps
#define NF 128      // num features
#define NSPLIT 8    // blocks per graph
#define SCALE_F 100.0f
#define R_F 1.1f

// Device globals (no allocation allowed). g_T is zero-initialized at module
// load; the epilogue re-zeroes each element after consuming it, so the
// all-zeros invariant holds at the start of every kernel_launch call.
__device__ float g_T[NG * NT * NS];   // [g][t][s]: sum of tanh terms
__device__ int   g_offs[NG + 1];      // graph start offsets (recomputed per call)

// batch may be int32 (JAX default) or int64 (reference dtype). n_nodes is the
// LOGICAL element count (derived from x). Probe the int32 word at n-1: for
// int64 it is the high half of element (n-1)/2 (== 0, ids < 128); for int32
// it is the last (largest, sorted) graph id != 0. In-bounds either way.
__device__ __forceinline__ bool batch_is_i64(const int* b32, int n_nodes) {
    return b32[n_nodes - 1] == 0;
}

__device__ int lower_bound_batch(const int* b32, int n, int key, bool is64) {
    const long long* b64 = (const long long*)b32;
    int lo = 0, hi = n;
    while (lo < hi) {
        int m = (lo + hi) >> 1;
        long long val = is64 ? b64[m] : (long long)b32[m];
        if (val < (long long)key) lo = m + 1; else hi = m;
    }
    return lo;
}

// One search per thread; 129 threads cover all boundaries. Runs once per call
// so every main/epilogue block reads offsets instead of binary-searching.
__global__ void offsets_kernel(const int* __restrict__ batch, int n_nodes) {
    int t = threadIdx.x;
    bool is64 = batch_is_i64(batch, n_nodes);
    if (t <= NG) g_offs[t] = lower_bound_batch(batch, n_nodes, t, is64);
}

__device__ __forceinline__ float tanh_ap(float xv) {
    float y;
    asm("tanh.approx.f32 %0, %1;" : "=f"(y) : "f"(xv));
    return y;
}

// Packed dual-FMA: d.lo += a.lo*b.lo; d.hi += a.hi*b.hi  (one FFMA2 issue)
__device__ __forceinline__ void ffma2(unsigned long long& d,
                                      unsigned long long a,
                                      unsigned long long b) {
    asm("fma.rn.f32x2 %0, %1, %2, %0;" : "+l"(d) : "l"(a), "l"(b));
}

__device__ __forceinline__ void cp_async16(uint32_t dst_smem, const void* src,
                                           int src_bytes) {
    // cg = bypass L1 (x is streamed, no reuse). src_bytes 0 -> zero-fill.
    asm volatile("cp.async.cg.shared.global [%0], [%1], 16, %2;"
                 :: "r"(dst_smem), "l"(src), "r"(src_bytes));
}

__global__ __launch_bounds__(256)
void ect_main_kernel(const float* __restrict__ x,
                     const float* __restrict__ v) {
    __shared__ float vP[NF / 2][NT][2];   // 16 KB: k-pair-packed v
    __shared__ float xs[2][32][132];      // 33.8 KB double buffer, pad 4

    const int tid  = threadIdx.x;
    const int lane = tid & 31;   // node-in-chunk (matmul) / s (transpose)
    const int w    = tid >> 5;   // warp id 0..7
    const int tb   = w * 4;      // this warp covers thetas tb..tb+3
    const int g    = blockIdx.x;

    // Pack v (vectorized): v is [NT][NF] row-major -> vP[k>>1][t][k&1]
    for (int i4 = tid; i4 < NF * NT / 4; i4 += 256) {
        float4 vv = ((const float4*)v)[i4];
        int t = i4 >> 5;          // (i4*4) / NF
        int k = (i4 & 31) * 4;    // even
        *(float2*)&vP[(k >> 1) + 0][t][0] = make_float2(vv.x, vv.y);
        *(float2*)&vP[(k >> 1) + 1][t][0] = make_float2(vv.z, vv.w);
    }

    const int glo = g_offs[g];
    const int ghi = g_offs[g + 1];
    const int len = ghi - glo;
    const int start = glo + (int)(((long long)len * blockIdx.y) / NSPLIT);
    const int end   = glo + (int)(((long long)len * (blockIdx.y + 1)) / NSPLIT);

    const float step = (2.0f * R_F) / (NS - 1);
    const float Cs = 0.5f * SCALE_F * (-R_F + lane * step);  // |Cs| <= 55
    // |hh| > TH  =>  |Cs - hh| > 17  =>  tanh == -sign(hh) exactly (fp32).
    const float TH = 72.0f;

    float acc0 = 0.f, acc1 = 0.f, acc2 = 0.f, acc3 = 0.f;
    int   net0 = 0,   net1 = 0,   net2 = 0,   net3 = 0;

    const int nch = (end > start) ? ((end - start + 31) >> 5) : 0;

    // Issue one 32-node chunk (16 KB) into buffer b via cp.async (4 per thread)
    #define ISSUE_CHUNK(ci, b)                                               \
        {                                                                    \
            int _base = start + (ci) * 32;                                   \
            _Pragma("unroll")                                                \
            for (int _j = 0; _j < 4; ++_j) {                                 \
                int _i4 = tid + _j * 256;                                    \
                int _n = _i4 >> 5, _k4 = _i4 & 31;                           \
                int _node = _base + _n;                                      \
                int _ok = (_node < end);                                     \
                const float4* _src = ((const float4*)x) +                    \
                    ((long long)(_ok ? _node : 0) * 32 + _k4);               \
                uint32_t _dst = (uint32_t)__cvta_generic_to_shared(          \
                    &xs[b][_n][_k4 * 4]);                                    \
                cp_async16(_dst, _src, _ok ? 16 : 0);                        \
            }                                                                \
        }

    if (nch > 0) ISSUE_CHUNK(0, 0)
    asm volatile("cp.async.commit_group;");

    for (int ci = 0; ci < nch; ++ci) {
        const int b = ci & 1;
        __syncthreads();  // all warps done computing chunk ci-1 (buffer b^1)
        if (ci + 1 < nch) ISSUE_CHUNK(ci + 1, b ^ 1)
        asm volatile("cp.async.commit_group;");
        asm volatile("cp.async.wait_group 1;");  // chunk ci landed
        __syncthreads();  // visible block-wide

        // Matmul: h for (node=lane, thetas tb..tb+3) via packed f32x2 FMA.
        unsigned long long p0 = 0, p1 = 0, p2 = 0, p3 = 0;
        #pragma unroll 4
        for (int k4 = 0; k4 < 32; ++k4) {
            ulonglong2 xk = *(const ulonglong2*)&xs[b][lane][k4 * 4];
            ulonglong2 va = *(const ulonglong2*)&vP[2 * k4][tb][0];
            ulonglong2 vb = *(const ulonglong2*)&vP[2 * k4][tb + 2][0];
            ffma2(p0, xk.x, va.x); ffma2(p1, xk.x, va.y);
            ffma2(p2, xk.x, vb.x); ffma2(p3, xk.x, vb.y);
            ulonglong2 vc = *(const ulonglong2*)&vP[2 * k4 + 1][tb][0];
            ulonglong2 vd = *(const ulonglong2*)&vP[2 * k4 + 1][tb + 2][0];
            ffma2(p0, xk.y, vc.x); ffma2(p1, xk.y, vc.y);
            ffma2(p2, xk.y, vd.x); ffma2(p3, xk.y, vd.y);
        }
        float2 f0 = *(float2*)&p0, f1 = *(float2*)&p1;
        float2 f2 = *(float2*)&p2, f3 = *(float2*)&p3;
        float hh0 = 0.5f * SCALE_F * (f0.x + f0.y);
        float hh1 = 0.5f * SCALE_F * (f1.x + f1.y);
        float hh2 = 0.5f * SCALE_F * (f2.x + f2.y);
        float hh3 = 0.5f * SCALE_F * (f3.x + f3.y);

        // Warp transpose with saturation skip: ballot classifies 32 nodes;
        // saturated ones fold into integer net; survivors (~34%) get
        // shfl + tanh via a warp-uniform bit-scan. Padded lanes masked out.
        const int nv = min(32, end - (start + ci * 32));
        const unsigned vmask = (nv >= 32) ? 0xffffffffu : ((1u << nv) - 1u);
        #define ECT_PROC(hh, acc, net)                                       \
            {                                                                \
                unsigned negm = __ballot_sync(0xffffffffu, (hh) < -TH) & vmask; \
                unsigned posm = __ballot_sync(0xffffffffu, (hh) >  TH) & vmask; \
                (net) += __popc(negm) - __popc(posm);                        \
                unsigned m = vmask & ~negm & ~posm;                          \
                while (m) {                                                  \
                    int r = __ffs(m) - 1;                                    \
                    m &= m - 1;                                              \
                    float bb = __shfl_sync(0xffffffffu, (hh), r);            \
                    (acc) += tanh_ap(Cs - bb);                               \
                }                                                            \
            }
        ECT_PROC(hh0, acc0, net0)
        ECT_PROC(hh1, acc1, net1)
        ECT_PROC(hh2, acc2, net2)
        ECT_PROC(hh3, acc3, net3)
        #undef ECT_PROC
    }
    #undef ISSUE_CHUNK

    // Single flush per warp: coalesced global float atomics (REDG), [g][t][s]
    atomicAdd(&g_T[(g * NT + tb + 0) * NS + lane], acc0 + (float)net0);
    atomicAdd(&g_T[(g * NT + tb + 1) * NS + lane], acc1 + (float)net1);
    atomicAdd(&g_T[(g * NT + tb + 2) * NS + lane], acc2 + (float)net2);
    atomicAdd(&g_T[(g * NT + tb + 3) * NS + lane], acc3 + (float)net3);
}

// Epilogue: sigma-sum = 0.5*cnt + 0.5*T; subtract cnt * sigmoid(100*(lin_s-R))
// (the exact constant pad term). Output layout [g][s][t]. Re-zeroes g_T so the
// next call starts from the all-zeros invariant (replaces zero_kernel).
__global__ void ect_epilogue_kernel(float* __restrict__ out) {
    int g = blockIdx.x;
    int t = threadIdx.x;  // 32 threads
    float cnt = (float)(g_offs[g + 1] - g_offs[g]);
    const float step = (2.0f * R_F) / (NS - 1);
    for (int s = 0; s < NS; s++) {
        int idx = (g * NT + t) * NS + s;
        float T = g_T[idx];
        g_T[idx] = 0.0f;
        float z0 = SCALE_F * ((-R_F + s * step) - R_F);
        float s0 = 1.0f / (1.0f + expf(-z0));   // exact constant pad term
        out[(g * NS + s) * NT + t] = 0.5f * cnt + 0.5f * T - cnt * s0;
    }
}

extern "C" void kernel_launch(void* const* d_in, const int* in_sizes, int n_in,
                              void* d_out, int out_size) {
    const float* x     = (const float*)d_in[0];
    const int*   batch = (const int*)d_in[1];   // int32 or int64, sniffed on device
    const float* v     = (const float*)d_in[3];
    // Derive node count from x ([N, 128] float32) — immune to how the harness
    // counts int64 elements for the batch array.
    int n_nodes = in_sizes[0] / NF;

    offsets_kernel<<<1, 160>>>(batch, n_nodes);
    dim3 grid(NG, NSPLIT);
    ect_main_kernel<<<grid, 256>>>(x, v);
    ect_epilogue_kernel<<<NG, 32>>>((float*)d_out);
}

// round 12
// speedup vs baseline: 1.1083x; 1.1083x over previous
#include <cuda_runtime.h>
#include <cstdint>

// Problem constants (fixed by the reference)
#define NG 128      // num_graphs
#define NT 32       // num thetas
#define NS 32       // bump steps
#define NF 128      // num features
#define SCALE_F 100.0f
#define R_F 1.1f

// Device globals (no allocation allowed). g_T is zero-initialized at module
// load; the epilogue re-zeroes each element after consuming it, so the
// all-zeros invariant holds at the start of every kernel_launch call.
__device__ float g_T[NG * NT * NS];   // [g][t][s]: sum of tanh terms
__device__ int   g_offs[NG + 1];      // graph start offsets (recomputed per call)

// batch may be int32 (JAX default) or int64 (reference dtype). n_nodes is the
// LOGICAL element count (derived from x). Probe the int32 word at n-1: for
// int64 it is the high half of element (n-1)/2 (== 0, ids < 128); for int32
// it is the last (largest, sorted) graph id != 0. In-bounds either way.
__device__ __forceinline__ bool batch_is_i64(const int* b32, int n_nodes) {
    return b32[n_nodes - 1] == 0;
}

__device__ __forceinline__ int load_id(const int* b, long long i, bool is64) {
    return is64 ? (int)((const long long*)b)[i] : b[i];
}

// O(n) offsets scan: thread i looks at (id[i], id[i+1]); on a change writes
// every boundary in the gap (handles empty graphs). g_offs[g] = lower_bound.
__global__ void offsets_scan_kernel(const int* __restrict__ batch, int n) {
    bool is64 = batch_is_i64(batch, n);
    for (int i = blockIdx.x * blockDim.x + threadIdx.x; i < n;
         i += gridDim.x * blockDim.x) {
        int bi = load_id(batch, i, is64);
        int bn = (i + 1 < n) ? load_id(batch, i + 1, is64) : NG;
        if (i == 0)
            for (int g = 0; g <= bi; ++g) g_offs[g] = 0;
        if (bn != bi)
            for (int g = bi + 1; g <= bn; ++g) g_offs[g] = i + 1;
    }
}

__device__ __forceinline__ float tanh_ap(float xv) {
    float y;
    asm("tanh.approx.f32 %0, %1;" : "=f"(y) : "f"(xv));
    return y;
}

// Packed dual-FMA: d.lo += a.lo*b.lo; d.hi += a.hi*b.hi  (one FFMA2 issue)
__device__ __forceinline__ void ffma2(unsigned long long& d,
                                      unsigned long long a,
                                      unsigned long long b) {
    asm("fma.rn.f32x2 %0, %1, %2, %0;" : "+l"(d) : "l"(a), "l"(b));
}

__device__ __forceinline__ void cp_async16(uint32_t dst_smem, const void* src,
                                           int src_bytes) {
    asm volatile("cp.async.cg.shared.global [%0], [%1], 16, %2;"
                 :: "r"(dst_smem), "l"(src), "r"(src_bytes));
}

// Dynamic smem: [vP: NF/2 * NT * 2 floats][xs: 2 * 32 * 132 floats] = 50176 B
#define SMEM_BYTES ((NF / 2 * NT * 2 + 2 * 32 * 132) * 4)

__global__ __launch_bounds__(256)
void ect_main_kernel(const float* __restrict__ x,
                     const int* __restrict__ batch,
                     int n_nodes,
                     const float* __restrict__ v,
                     int npb) {
    extern __shared__ float dyn[];
    float (*vP)[NT][2]  = (float(*)[NT][2])dyn;              // k-pair-packed v
    float (*xs)[32][132] = (float(*)[32][132])(dyn + 4096);  // double buffer

    const int tid  = threadIdx.x;
    const int lane = tid & 31;   // node-in-chunk (matmul) / s (transpose)
    const int w    = tid >> 5;   // warp id 0..7
    const int tb   = w * 4;      // this warp covers thetas tb..tb+3

    const bool is64 = batch_is_i64(batch, n_nodes);

    // Pack v (vectorized): v is [NT][NF] row-major -> vP[k>>1][t][k&1]
    for (int i4 = tid; i4 < NF * NT / 4; i4 += 256) {
        float4 vv = ((const float4*)v)[i4];
        int t = i4 >> 5;
        int k = (i4 & 31) * 4;
        *(float2*)&vP[(k >> 1) + 0][t][0] = make_float2(vv.x, vv.y);
        *(float2*)&vP[(k >> 1) + 1][t][0] = make_float2(vv.z, vv.w);
    }

    // Flat contiguous node range for this block (equal work, no graph align)
    const int bstart = blockIdx.x * npb;
    const int bend   = min(n_nodes, bstart + npb);
    const int nch    = (bend > bstart) ? ((bend - bstart + 31) >> 5) : 0;

    const float step = (2.0f * R_F) / (NS - 1);
    const float Cs = 0.5f * SCALE_F * (-R_F + lane * step);  // |Cs| <= 55
    // |hh| > TH  =>  |Cs - hh| > 17  =>  tanh == -sign(hh) exactly (fp32).
    const float TH = 72.0f;

    float acc0 = 0.f, acc1 = 0.f, acc2 = 0.f, acc3 = 0.f;
    int   net0 = 0,   net1 = 0,   net2 = 0,   net3 = 0;
    // Current graph this warp is accumulating for (sorted batch => runs)
    int cur_g = (bstart < n_nodes) ? load_id(batch, bstart, is64) : 0;

    #define ISSUE_CHUNK(ci, b)                                               \
        {                                                                    \
            int _base = bstart + (ci) * 32;                                  \
            _Pragma("unroll")                                                \
            for (int _j = 0; _j < 4; ++_j) {                                 \
                int _i4 = tid + _j * 256;                                    \
                int _n = _i4 >> 5, _k4 = _i4 & 31;                           \
                int _node = _base + _n;                                      \
                int _ok = (_node < bend);                                    \
                const float4* _src = ((const float4*)x) +                    \
                    ((long long)(_ok ? _node : 0) * 32 + _k4);               \
                uint32_t _dst = (uint32_t)__cvta_generic_to_shared(          \
                    &xs[b][_n][_k4 * 4]);                                    \
                cp_async16(_dst, _src, _ok ? 16 : 0);                        \
            }                                                                \
        }

    #define ECT_PROC(hh, acc, net, pm)                                       \
        {                                                                    \
            unsigned negm = __ballot_sync(0xffffffffu, (hh) < -TH) & (pm);   \
            unsigned posm = __ballot_sync(0xffffffffu, (hh) >  TH) & (pm);   \
            (net) += __popc(negm) - __popc(posm);                            \
            unsigned m = (pm) & ~negm & ~posm;                               \
            while (m) {                                                      \
                int r = __ffs(m) - 1;                                        \
                m &= m - 1;                                                  \
                float bb = __shfl_sync(0xffffffffu, (hh), r);                \
                (acc) += tanh_ap(Cs - bb);                                   \
            }                                                                \
        }

    #define FLUSH_ACC()                                                      \
        {                                                                    \
            atomicAdd(&g_T[(cur_g * NT + tb + 0) * NS + lane],               \
                      acc0 + (float)net0);                                   \
            atomicAdd(&g_T[(cur_g * NT + tb + 1) * NS + lane],               \
                      acc1 + (float)net1);                                   \
            atomicAdd(&g_T[(cur_g * NT + tb + 2) * NS + lane],               \
                      acc2 + (float)net2);                                   \
            atomicAdd(&g_T[(cur_g * NT + tb + 3) * NS + lane],               \
                      acc3 + (float)net3);                                   \
        }

    if (nch > 0) ISSUE_CHUNK(0, 0)
    asm volatile("cp.async.commit_group;");

    for (int ci = 0; ci < nch; ++ci) {
        const int b = ci & 1;
        __syncthreads();  // prev chunk's compute done (buffer b^1 reusable)
        if (ci + 1 < nch) ISSUE_CHUNK(ci + 1, b ^ 1)
        asm volatile("cp.async.commit_group;");
        asm volatile("cp.async.wait_group 1;");  // chunk ci landed
        __syncthreads();

        // Matmul: h for (node=lane, thetas tb..tb+3) via packed f32x2 FMA.
        unsigned long long p0 = 0, p1 = 0, p2 = 0, p3 = 0;
        #pragma unroll 4
        for (int k4 = 0; k4 < 32; ++k4) {
            ulonglong2 xk = *(const ulonglong2*)&xs[b][lane][k4 * 4];
            ulonglong2 va = *(const ulonglong2*)&vP[2 * k4][tb][0];
            ulonglong2 vb = *(const ulonglong2*)&vP[2 * k4][tb + 2][0];
            ffma2(p0, xk.x, va.x); ffma2(p1, xk.x, va.y);
            ffma2(p2, xk.x, vb.x); ffma2(p3, xk.x, vb.y);
            ulonglong2 vc = *(const ulonglong2*)&vP[2 * k4 + 1][tb][0];
            ulonglong2 vd = *(const ulonglong2*)&vP[2 * k4 + 1][tb + 2][0];
            ffma2(p0, xk.y, vc.x); ffma2(p1, xk.y, vc.y);
            ffma2(p2, xk.y, vd.x); ffma2(p3, xk.y, vd.y);
        }
        float2 f0 = *(float2*)&p0, f1 = *(float2*)&p1;
        float2 f2 = *(float2*)&p2, f3 = *(float2*)&p3;
        float hh0 = 0.5f * SCALE_F * (f0.x + f0.y);
        float hh1 = 0.5f * SCALE_F * (f1.x + f1.y);
        float hh2 = 0.5f * SCALE_F * (f2.x + f2.y);
        float hh3 = 0.5f * SCALE_F * (f3.x + f3.y);

        // Graph-run handling: chunk is sorted; 98% of chunks are one graph.
        const int base = bstart + ci * 32;
        const int nv = min(32, bend - base);
        const unsigned vmask = (nv >= 32) ? 0xffffffffu : ((1u << nv) - 1u);
        int myid = cur_g;
        if (lane < nv) myid = load_id(batch, base + lane, is64);

        unsigned mcur = __ballot_sync(0xffffffffu, myid == cur_g) & vmask;
        if (mcur == vmask) {
            // Fast path: whole chunk belongs to cur_g
            ECT_PROC(hh0, acc0, net0, vmask)
            ECT_PROC(hh1, acc1, net1, vmask)
            ECT_PROC(hh2, acc2, net2, vmask)
            ECT_PROC(hh3, acc3, net3, vmask)
        } else {
            // Slow path (~2% of chunks): process runs, flush at boundaries
            unsigned rem = vmask;
            while (rem) {
                mcur = __ballot_sync(0xffffffffu, myid == cur_g) & rem;
                ECT_PROC(hh0, acc0, net0, mcur)
                ECT_PROC(hh1, acc1, net1, mcur)
                ECT_PROC(hh2, acc2, net2, mcur)
                ECT_PROC(hh3, acc3, net3, mcur)
                rem &= ~mcur;
                if (rem) {
                    FLUSH_ACC();
                    acc0 = acc1 = acc2 = acc3 = 0.f;
                    net0 = net1 = net2 = net3 = 0;
                    int nxt = __ffs(rem) - 1;
                    cur_g = __shfl_sync(0xffffffffu, myid, nxt);
                }
            }
        }
    }

    if (bstart < n_nodes) FLUSH_ACC();

    #undef ISSUE_CHUNK
    #undef ECT_PROC
    #undef FLUSH_ACC
}

// Epilogue: sigma-sum = 0.5*cnt + 0.5*T; subtract cnt * sigmoid(100*(lin_s-R))
// (the exact constant pad term). Output layout [g][s][t]. Re-zeroes g_T so the
// next call starts from the all-zeros invariant.
__global__ void ect_epilogue_kernel(float* __restrict__ out) {
    int g = blockIdx.x;
    int t = threadIdx.x;  // 32 threads
    float cnt = (float)(g_offs[g + 1] - g_offs[g]);
    const float step = (2.0f * R_F) / (NS - 1);
    for (int s = 0; s < NS; s++) {
        int idx = (g * NT + t) * NS + s;
        float T = g_T[idx];
        g_T[idx] = 0.0f;
        float z0 = SCALE_F * ((-R_F + s * step) - R_F);
        float s0 = 1.0f / (1.0f + expf(-z0));   // exact constant pad term
        out[(g * NS + s) * NT + t] = 0.5f * cnt + 0.5f * T - cnt * s0;
    }
}

extern "C" void kernel_launch(void* const* d_in, const int* in_sizes, int n_in,
                              void* d_out, int out_size) {
    const float* x     = (const float*)d_in[0];
    const int*   batch = (const int*)d_in[1];   // int32 or int64, sniffed on device
    const float* v     = (const float*)d_in[3];
    int n_nodes = in_sizes[0] / NF;   // from x [N,128] f32 (dtype-unambiguous)

    // Balanced flat decomposition: ~4 blocks/SM * 148 SMs target, 32-aligned
    const int target_blocks = 592;
    int npb = ((n_nodes + target_blocks - 1) / target_blocks + 31) & ~31;
    if (npb < 32) npb = 32;
    int blocks = (n_nodes + npb - 1) / npb;

    cudaFuncSetAttribute(ect_main_kernel,
                         cudaFuncAttributeMaxDynamicSharedMemorySize,
                         SMEM_BYTES);

    offsets_scan_kernel<<<256, 256>>>(batch, n_nodes);
    ect_main_kernel<<<blocks, 256, SMEM_BYTES>>>(x, batch, n_nodes, v, npb);
    ect_epilogue_kernel<<<NG, 32>>>((float*)d_out);
}